// round 7
// baseline (speedup 1.0000x reference)
#include <cuda_runtime.h>
#include <cstdint>

#define K_DIM 4096
#define N_DIM 8192
#define INFCAP 100.0f
#define BP_EPS 1e-4f

// ---------------- scratch (no allocation allowed) ----------------
__device__ float g_colsum[N_DIM];   // sum_k Hxs[k,n]
__device__ float g_colsum2[N_DIM];  // sum_k Hxs_new[k,n]
__device__ float g_prior[N_DIM];    // clip(dope+phi+colsum, +-INFCAP)
__device__ float g_dope[N_DIM];     // doping LLR
__device__ float g_prod[K_DIM];     // per-row tanh product (0 => row output is exactly 0)

__device__ __forceinline__ float tanh_approx(float x) {
    float r;
    asm("tanh.approx.f32 %0, %1;" : "=f"(r) : "f"(x));
    return r;
}

// ---------------- K0: zero accumulators ----------------
__global__ void k_zero() {
    int i = blockIdx.x * blockDim.x + threadIdx.x;
    if (i < N_DIM) { g_colsum[i] = 0.f; g_colsum2[i] = 0.f; }
}

// ---------------- K1: column sum of Hxs ----------------
__global__ __launch_bounds__(256) void k_colsum(const float* __restrict__ M) {
    const int ROWS = 64;
    int cbase = blockIdx.x * 1024 + threadIdx.x * 4;
    int r0 = blockIdx.y * ROWS;
    const float4* p = (const float4*)(M + (size_t)r0 * N_DIM + cbase);
    float4 a = make_float4(0.f, 0.f, 0.f, 0.f);
#pragma unroll 8
    for (int r = 0; r < ROWS; r++) {
        float4 v = p[(size_t)r * (N_DIM / 4)];
        a.x += v.x; a.y += v.y; a.z += v.z; a.w += v.w;
    }
    atomicAdd(&g_colsum[cbase + 0], a.x);
    atomicAdd(&g_colsum[cbase + 1], a.y);
    atomicAdd(&g_colsum[cbase + 2], a.z);
    atomicAdd(&g_colsum[cbase + 3], a.w);
}

// ---------------- K1b: dope / phi / prior ----------------
__global__ void k_prior(const float* __restrict__ ps, const float* __restrict__ Min) {
    int n = blockIdx.x * blockDim.x + threadIdx.x;
    if (n >= N_DIM) return;
    float p0 = ps[2 * n], p1 = ps[2 * n + 1];
    float pn = p1 / (p0 + p1);
    float dope = logf(1.f - pn) - logf(pn);
    float m0 = Min[2 * n], m1 = Min[2 * n + 1];
    float mn = m1 / (m0 + m1);
    float phi = logf(1.f - mn) - logf(mn);
    g_dope[n] = dope;
    float pr = dope + phi + g_colsum[n];
    g_prior[n] = fminf(fmaxf(pr, -INFCAP), INFCAP);
}

// ---------------- helpers ----------------
__device__ __forceinline__ float bp_elem(float t, float prod, float s) {
    if (t == 0.f) return 0.f;                        // zero-mask -> arctanh(0) -> 0
    float y = s * __fdividef(prod, t);               // (1-2x) * prodtanhm / tanhm
    y = fminf(fmaxf(y, -1.f), 1.f);
    float r = __logf(__fdividef(1.f + y, 1.f - y));  // 2*atanh(y); +-inf at endpoints
    return fminf(fmaxf(r, -1.f), 1.f);               // clip absorbs inf
}

__device__ __forceinline__ float t_elem(int h, float pr, float hx) {
    return tanh_approx(0.5f * (h ? (pr + BP_EPS - hx) : -hx));
}

// ---------------- K2a: per-row tanh product (READ-ONLY stream) ----------------
// One CTA (512 threads) per check row: reads Hxs+H (268 MB total), writes one
// float per row. Pure read direction keeps DRAM in streaming mode.
__global__ __launch_bounds__(512) void k_prod(const float* __restrict__ Hxs,
                                              const int* __restrict__ H) {
    __shared__ float warp_prod[16];
    int k = blockIdx.x;
    int tid = threadIdx.x;

    const float4* hx4 = (const float4*)(Hxs + (size_t)k * N_DIM);
    const int4*   h4  = (const int4*)(H + (size_t)k * N_DIM);
    const float4* pr4 = (const float4*)g_prior;

    float p = 1.f;
#pragma unroll
    for (int i = 0; i < 4; i++) {
        int idx = tid + i * 512;
        float4 hx = hx4[idx];
        int4   h  = h4[idx];
        float4 pr = pr4[idx];
        float tx = t_elem(h.x, pr.x, hx.x);
        float ty = t_elem(h.y, pr.y, hx.y);
        float tz = t_elem(h.z, pr.z, hx.z);
        float tw = t_elem(h.w, pr.w, hx.w);
        p *= ((tx == 0.f) ? 1.f : tx) * ((ty == 0.f) ? 1.f : ty)
           * ((tz == 0.f) ? 1.f : tz) * ((tw == 0.f) ? 1.f : tw);
    }

#pragma unroll
    for (int off = 16; off; off >>= 1) p *= __shfl_xor_sync(0xffffffffu, p, off);
    if ((tid & 31) == 0) warp_prod[tid >> 5] = p;
    __syncthreads();
    if (tid < 16) {
        float q = warp_prod[tid];
#pragma unroll
        for (int off = 8; off; off >>= 1) q *= __shfl_xor_sync(0x0000ffffu, q, off);
        if (tid == 0) g_prod[k] = q;
    }
}

// ---------------- K2b: output writer (WRITE-ONLY stream on fast path) ----------
// prod == 0 (fp32 underflow of ~4096 |t|<1 factors -- the common case): every
// output of the row is EXACTLY clip(2*atanh(+-0)) = 0 -> pure zero-write, no
// loads, no barriers. prod != 0 (general inputs): re-read the row and compute
// the exact leave-one-out values.
__global__ __launch_bounds__(512) void k_write(const float* __restrict__ Hxs,
                                               const int* __restrict__ H,
                                               const int* __restrict__ x,
                                               float* __restrict__ out_Hxs) {
    int k = blockIdx.x;
    int tid = threadIdx.x;
    float prod = g_prod[k];
    float4* o4 = (float4*)(out_Hxs + (size_t)k * N_DIM);

    if (prod == 0.f) {
        float4 z = make_float4(0.f, 0.f, 0.f, 0.f);
#pragma unroll
        for (int i = 0; i < 4; i++) o4[tid + i * 512] = z;
    } else {
        const float4* hx4 = (const float4*)(Hxs + (size_t)k * N_DIM);
        const int4*   h4  = (const int4*)(H + (size_t)k * N_DIM);
        const float4* pr4 = (const float4*)g_prior;
        float s = (float)(1 - 2 * x[k]);
#pragma unroll
        for (int i = 0; i < 4; i++) {
            int idx = tid + i * 512;
            float4 hx = hx4[idx];
            int4   h  = h4[idx];
            float4 pr = pr4[idx];
            float4 o;
            o.x = bp_elem(t_elem(h.x, pr.x, hx.x), prod, s);
            o.y = bp_elem(t_elem(h.y, pr.y, hx.y), prod, s);
            o.z = bp_elem(t_elem(h.z, pr.z, hx.z), prod, s);
            o.w = bp_elem(t_elem(h.w, pr.w, hx.w), prod, s);
            o4[idx] = o;
        }
    }
}

// ---------------- K3: column sum of Hxs_new, skipping all-zero rows ----------------
__global__ __launch_bounds__(256) void k_colsum2(const float* __restrict__ M) {
    const int ROWS = 64;
    int cbase = blockIdx.x * 1024 + threadIdx.x * 4;
    int r0 = blockIdx.y * ROWS;
    const float4* p = (const float4*)(M + (size_t)r0 * N_DIM + cbase);
    float4 a = make_float4(0.f, 0.f, 0.f, 0.f);
    bool any = false;
    for (int r = 0; r < ROWS; r++) {
        if (g_prod[r0 + r] != 0.f) {      // zero-product rows are exactly 0: skip
            any = true;
            float4 v = p[(size_t)r * (N_DIM / 4)];
            a.x += v.x; a.y += v.y; a.z += v.z; a.w += v.w;
        }
    }
    if (any) {
        atomicAdd(&g_colsum2[cbase + 0], a.x);
        atomicAdd(&g_colsum2[cbase + 1], a.y);
        atomicAdd(&g_colsum2[cbase + 2], a.z);
        atomicAdd(&g_colsum2[cbase + 3], a.w);
    }
}

// ---------------- K4: output beliefs ----------------
__global__ void k_out(float* __restrict__ out_M) {
    int n = blockIdx.x * blockDim.x + threadIdx.x;
    if (n >= N_DIM) return;
    float z = (1.f - tanhf((g_colsum2[n] + g_dope[n]) * 0.5f)) * 0.5f;
    out_M[2 * n + 0] = 1.f - z;
    out_M[2 * n + 1] = z;
}

extern "C" void kernel_launch(void* const* d_in, const int* in_sizes, int n_in,
                              void* d_out, int out_size) {
    const float* ps  = (const float*)d_in[0];
    const float* Min = (const float*)d_in[1];
    const float* Hxs = (const float*)d_in[2];
    const int*   x   = (const int*)d_in[3];
    const int*   H   = (const int*)d_in[4];

    float* out     = (float*)d_out;
    float* out_M   = out;                 // M_out [N,2] first
    float* out_Hxs = out + 2 * N_DIM;     // Hxs_new [K,N] second

    k_zero<<<N_DIM / 256, 256>>>();
    k_colsum<<<dim3(N_DIM / 1024, K_DIM / 64), 256>>>(Hxs);
    k_prior<<<N_DIM / 256, 256>>>(ps, Min);
    k_prod<<<K_DIM, 512>>>(Hxs, H);
    k_write<<<K_DIM, 512>>>(Hxs, H, x, out_Hxs);
    k_colsum2<<<dim3(N_DIM / 1024, K_DIM / 64), 256>>>(out_Hxs);
    k_out<<<N_DIM / 256, 256>>>(out_M);
}

// round 8
// speedup vs baseline: 1.0093x; 1.0093x over previous
#include <cuda_runtime.h>
#include <cstdint>

#define K_DIM 4096
#define N_DIM 8192
#define INFCAP 100.0f
#define BP_EPS 1e-4f

// ---------------- scratch (no allocation allowed) ----------------
__device__ float g_colsum[N_DIM];   // sum_k Hxs[k,n]
__device__ float g_colsum2[N_DIM];  // sum_k Hxs_new[k,n]
__device__ float g_prior[N_DIM];    // clip(dope+phi+colsum, +-INFCAP)
__device__ float g_dope[N_DIM];     // doping LLR
__device__ float g_prod[K_DIM];     // per-row tanh product (0 => row output is exactly 0)

__device__ __forceinline__ float tanh_approx(float x) {
    float r;
    asm("tanh.approx.f32 %0, %1;" : "=f"(r) : "f"(x));
    return r;
}

// ---------------- K0: zero accumulators ----------------
__global__ void k_zero() {
    int i = blockIdx.x * blockDim.x + threadIdx.x;
    if (i < N_DIM) { g_colsum[i] = 0.f; g_colsum2[i] = 0.f; }
}

// ---------------- K1: column sum of Hxs ----------------
__global__ __launch_bounds__(256) void k_colsum(const float* __restrict__ M) {
    const int ROWS = 64;
    int cbase = blockIdx.x * 1024 + threadIdx.x * 4;
    int r0 = blockIdx.y * ROWS;
    const float4* p = (const float4*)(M + (size_t)r0 * N_DIM + cbase);
    float4 a = make_float4(0.f, 0.f, 0.f, 0.f);
#pragma unroll 8
    for (int r = 0; r < ROWS; r++) {
        float4 v = p[(size_t)r * (N_DIM / 4)];
        a.x += v.x; a.y += v.y; a.z += v.z; a.w += v.w;
    }
    atomicAdd(&g_colsum[cbase + 0], a.x);
    atomicAdd(&g_colsum[cbase + 1], a.y);
    atomicAdd(&g_colsum[cbase + 2], a.z);
    atomicAdd(&g_colsum[cbase + 3], a.w);
}

// ---------------- K1b: dope / phi / prior ----------------
__global__ void k_prior(const float* __restrict__ ps, const float* __restrict__ Min) {
    int n = blockIdx.x * blockDim.x + threadIdx.x;
    if (n >= N_DIM) return;
    float p0 = ps[2 * n], p1 = ps[2 * n + 1];
    float pn = p1 / (p0 + p1);
    float dope = logf(1.f - pn) - logf(pn);
    float m0 = Min[2 * n], m1 = Min[2 * n + 1];
    float mn = m1 / (m0 + m1);
    float phi = logf(1.f - mn) - logf(mn);
    g_dope[n] = dope;
    float pr = dope + phi + g_colsum[n];
    g_prior[n] = fminf(fmaxf(pr, -INFCAP), INFCAP);
}

// ---------------- helpers ----------------
__device__ __forceinline__ float bp_elem(float t, float prod, float s) {
    if (t == 0.f) return 0.f;                        // zero-mask -> arctanh(0) -> 0
    float y = s * __fdividef(prod, t);               // (1-2x) * prodtanhm / tanhm
    y = fminf(fmaxf(y, -1.f), 1.f);
    float r = __logf(__fdividef(1.f + y, 1.f - y));  // 2*atanh(y); +-inf at endpoints
    return fminf(fmaxf(r, -1.f), 1.f);               // clip absorbs inf
}

__device__ __forceinline__ float t_elem(int h, float pr, float hx) {
    return tanh_approx(0.5f * (h ? (pr + BP_EPS - hx) : -hx));
}

// ---------------- K2a: per-row tanh product (READ-ONLY stream) ----------------
// One CTA (512 threads) per check row: reads Hxs+H (268 MB total), writes one
// float per row. Pure read direction keeps DRAM in streaming mode.
__global__ __launch_bounds__(512) void k_prod(const float* __restrict__ Hxs,
                                              const int* __restrict__ H) {
    __shared__ float warp_prod[16];
    int k = blockIdx.x;
    int tid = threadIdx.x;

    const float4* hx4 = (const float4*)(Hxs + (size_t)k * N_DIM);
    const int4*   h4  = (const int4*)(H + (size_t)k * N_DIM);
    const float4* pr4 = (const float4*)g_prior;

    float p = 1.f;
#pragma unroll
    for (int i = 0; i < 4; i++) {
        int idx = tid + i * 512;
        float4 hx = hx4[idx];
        int4   h  = h4[idx];
        float4 pr = pr4[idx];
        float tx = t_elem(h.x, pr.x, hx.x);
        float ty = t_elem(h.y, pr.y, hx.y);
        float tz = t_elem(h.z, pr.z, hx.z);
        float tw = t_elem(h.w, pr.w, hx.w);
        p *= ((tx == 0.f) ? 1.f : tx) * ((ty == 0.f) ? 1.f : ty)
           * ((tz == 0.f) ? 1.f : tz) * ((tw == 0.f) ? 1.f : tw);
    }

#pragma unroll
    for (int off = 16; off; off >>= 1) p *= __shfl_xor_sync(0xffffffffu, p, off);
    if ((tid & 31) == 0) warp_prod[tid >> 5] = p;
    __syncthreads();
    if (tid < 16) {
        float q = warp_prod[tid];
#pragma unroll
        for (int off = 8; off; off >>= 1) q *= __shfl_xor_sync(0x0000ffffu, q, off);
        if (tid == 0) g_prod[k] = q;
    }
}

// ---------------- K2b: output writer (WRITE-ONLY stream on fast path) ----------
// prod == 0 (fp32 underflow of ~4096 |t|<1 factors -- the common case): every
// output of the row is EXACTLY clip(2*atanh(+-0)) = 0 -> pure zero-write, no
// loads, no barriers. prod != 0 (general inputs): re-read the row and compute
// the exact leave-one-out values.
__global__ __launch_bounds__(512) void k_write(const float* __restrict__ Hxs,
                                               const int* __restrict__ H,
                                               const int* __restrict__ x,
                                               float* __restrict__ out_Hxs) {
    int k = blockIdx.x;
    int tid = threadIdx.x;
    float prod = g_prod[k];
    float4* o4 = (float4*)(out_Hxs + (size_t)k * N_DIM);

    if (prod == 0.f) {
        float4 z = make_float4(0.f, 0.f, 0.f, 0.f);
#pragma unroll
        for (int i = 0; i < 4; i++) o4[tid + i * 512] = z;
    } else {
        const float4* hx4 = (const float4*)(Hxs + (size_t)k * N_DIM);
        const int4*   h4  = (const int4*)(H + (size_t)k * N_DIM);
        const float4* pr4 = (const float4*)g_prior;
        float s = (float)(1 - 2 * x[k]);
#pragma unroll
        for (int i = 0; i < 4; i++) {
            int idx = tid + i * 512;
            float4 hx = hx4[idx];
            int4   h  = h4[idx];
            float4 pr = pr4[idx];
            float4 o;
            o.x = bp_elem(t_elem(h.x, pr.x, hx.x), prod, s);
            o.y = bp_elem(t_elem(h.y, pr.y, hx.y), prod, s);
            o.z = bp_elem(t_elem(h.z, pr.z, hx.z), prod, s);
            o.w = bp_elem(t_elem(h.w, pr.w, hx.w), prod, s);
            o4[idx] = o;
        }
    }
}

// ---------------- K3: column sum of Hxs_new, skipping all-zero rows ----------------
__global__ __launch_bounds__(256) void k_colsum2(const float* __restrict__ M) {
    const int ROWS = 64;
    int cbase = blockIdx.x * 1024 + threadIdx.x * 4;
    int r0 = blockIdx.y * ROWS;
    const float4* p = (const float4*)(M + (size_t)r0 * N_DIM + cbase);
    float4 a = make_float4(0.f, 0.f, 0.f, 0.f);
    bool any = false;
    for (int r = 0; r < ROWS; r++) {
        if (g_prod[r0 + r] != 0.f) {      // zero-product rows are exactly 0: skip
            any = true;
            float4 v = p[(size_t)r * (N_DIM / 4)];
            a.x += v.x; a.y += v.y; a.z += v.z; a.w += v.w;
        }
    }
    if (any) {
        atomicAdd(&g_colsum2[cbase + 0], a.x);
        atomicAdd(&g_colsum2[cbase + 1], a.y);
        atomicAdd(&g_colsum2[cbase + 2], a.z);
        atomicAdd(&g_colsum2[cbase + 3], a.w);
    }
}

// ---------------- K4: output beliefs ----------------
__global__ void k_out(float* __restrict__ out_M) {
    int n = blockIdx.x * blockDim.x + threadIdx.x;
    if (n >= N_DIM) return;
    float z = (1.f - tanhf((g_colsum2[n] + g_dope[n]) * 0.5f)) * 0.5f;
    out_M[2 * n + 0] = 1.f - z;
    out_M[2 * n + 1] = z;
}

extern "C" void kernel_launch(void* const* d_in, const int* in_sizes, int n_in,
                              void* d_out, int out_size) {
    const float* ps  = (const float*)d_in[0];
    const float* Min = (const float*)d_in[1];
    const float* Hxs = (const float*)d_in[2];
    const int*   x   = (const int*)d_in[3];
    const int*   H   = (const int*)d_in[4];

    float* out     = (float*)d_out;
    float* out_M   = out;                 // M_out [N,2] first
    float* out_Hxs = out + 2 * N_DIM;     // Hxs_new [K,N] second

    k_zero<<<N_DIM / 256, 256>>>();
    k_colsum<<<dim3(N_DIM / 1024, K_DIM / 64), 256>>>(Hxs);
    k_prior<<<N_DIM / 256, 256>>>(ps, Min);
    k_prod<<<K_DIM, 512>>>(Hxs, H);
    k_write<<<K_DIM, 512>>>(Hxs, H, x, out_Hxs);
    k_colsum2<<<dim3(N_DIM / 1024, K_DIM / 64), 256>>>(out_Hxs);
    k_out<<<N_DIM / 256, 256>>>(out_M);
}

// round 10
// speedup vs baseline: 1.1712x; 1.1604x over previous
#include <cuda_runtime.h>
#include <cstdint>

#define K_DIM 4096
#define N_DIM 8192
#define INFCAP 100.0f
#define BP_EPS 1e-4f

// ---------------- scratch (no allocation allowed) ----------------
__device__ float g_colsum[N_DIM];   // sum_k Hxs[k,n]
__device__ float g_colsum2[N_DIM];  // sum_k Hxs_new[k,n]
__device__ float g_prior[N_DIM];    // clip(dope+phi+colsum, +-INFCAP)
__device__ float g_tanh[N_DIM];     // tanh(0.5*(prior+EPS)) -- fast-path column factor
__device__ float g_dope[N_DIM];     // doping LLR
__device__ float g_prod[K_DIM];     // per-row tanh product (0 => row output is exactly 0)
__device__ int   g_hxs_nonzero;     // 1 if any Hxs element != 0

__device__ __forceinline__ float tanh_approx(float x) {
    float r;
    asm("tanh.approx.f32 %0, %1;" : "=f"(r) : "f"(x));
    return r;
}

// ---------------- K0: zero accumulators ----------------
__global__ void k_zero() {
    int i = blockIdx.x * blockDim.x + threadIdx.x;
    if (i < N_DIM) { g_colsum[i] = 0.f; g_colsum2[i] = 0.f; }
    if (i == 0) g_hxs_nonzero = 0;
}

// ---------------- K1: column sum of Hxs + exact zero-detection ----------------
__global__ __launch_bounds__(256) void k_colsum(const float* __restrict__ M) {
    const int ROWS = 64;
    int cbase = blockIdx.x * 1024 + threadIdx.x * 4;
    int r0 = blockIdx.y * ROWS;
    const float4* p = (const float4*)(M + (size_t)r0 * N_DIM + cbase);
    float4 a = make_float4(0.f, 0.f, 0.f, 0.f);
    bool nz = false;
#pragma unroll 8
    for (int r = 0; r < ROWS; r++) {
        float4 v = p[(size_t)r * (N_DIM / 4)];
        a.x += v.x; a.y += v.y; a.z += v.z; a.w += v.w;
        nz = nz || (v.x != 0.f) || (v.y != 0.f) || (v.z != 0.f) || (v.w != 0.f);
    }
    atomicAdd(&g_colsum[cbase + 0], a.x);
    atomicAdd(&g_colsum[cbase + 1], a.y);
    atomicAdd(&g_colsum[cbase + 2], a.z);
    atomicAdd(&g_colsum[cbase + 3], a.w);
    // block-wide OR; atomic only fires if a nonzero was actually seen
    if (__syncthreads_or(nz) && threadIdx.x == 0) atomicOr(&g_hxs_nonzero, 1);
}

// ---------------- K1b: dope / phi / prior / fast-path column factor ----------------
__global__ void k_prior(const float* __restrict__ ps, const float* __restrict__ Min) {
    int n = blockIdx.x * blockDim.x + threadIdx.x;
    if (n >= N_DIM) return;
    float p0 = ps[2 * n], p1 = ps[2 * n + 1];
    float pn = p1 / (p0 + p1);
    float dope = logf(1.f - pn) - logf(pn);
    float m0 = Min[2 * n], m1 = Min[2 * n + 1];
    float mn = m1 / (m0 + m1);
    float phi = logf(1.f - mn) - logf(mn);
    g_dope[n] = dope;
    float pr = dope + phi + g_colsum[n];
    pr = fminf(fmaxf(pr, -INFCAP), INFCAP);
    g_prior[n] = pr;
    // bit-identical to t_elem(1, pr, 0.f): the Hxs==0 fast-path factor
    g_tanh[n] = tanh_approx(0.5f * (pr + BP_EPS));
}

// ---------------- helpers ----------------
__device__ __forceinline__ float bp_elem(float t, float prod, float s) {
    if (t == 0.f) return 0.f;                        // zero-mask -> arctanh(0) -> 0
    float y = s * __fdividef(prod, t);               // (1-2x) * prodtanhm / tanhm
    y = fminf(fmaxf(y, -1.f), 1.f);
    float r = __logf(__fdividef(1.f + y, 1.f - y));  // 2*atanh(y); +-inf at endpoints
    return fminf(fmaxf(r, -1.f), 1.f);               // clip absorbs inf
}

__device__ __forceinline__ float t_elem(int h, float pr, float hx) {
    return tanh_approx(0.5f * (h ? (pr + BP_EPS - hx) : -hx));
}

// ---------------- K2a: per-row tanh product ----------------
// Fast path (Hxs all zero, the given input): t for H=0 entries is tanh(-0)=0 ->
// zero-masked to factor 1; t for H=1 entries is g_tanh[n] (column-only). So the
// row product needs ONLY H (134 MB) -- bit-identical to the full computation.
// Slow path (general inputs): stream Hxs too, exact as before.
__global__ __launch_bounds__(512) void k_prod(const float* __restrict__ Hxs,
                                              const int* __restrict__ H) {
    __shared__ float warp_prod[16];
    int k = blockIdx.x;
    int tid = threadIdx.x;

    const int4*   h4  = (const int4*)(H + (size_t)k * N_DIM);
    const float4* pr4 = (const float4*)g_prior;
    const float4* th4 = (const float4*)g_tanh;

    float p = 1.f;
    if (g_hxs_nonzero == 0) {
        // ---- fast path: H only; g_tanh is L2-resident (32 KB) ----
#pragma unroll
        for (int i = 0; i < 4; i++) {
            int idx = tid + i * 512;
            int4   h = h4[idx];
            float4 t = th4[idx];
            p *= (h.x ? t.x : 1.f) * (h.y ? t.y : 1.f)
               * (h.z ? t.z : 1.f) * (h.w ? t.w : 1.f);
        }
    } else {
        // ---- slow path: general inputs ----
        const float4* hx4 = (const float4*)(Hxs + (size_t)k * N_DIM);
#pragma unroll
        for (int i = 0; i < 4; i++) {
            int idx = tid + i * 512;
            float4 hx = hx4[idx];
            int4   h  = h4[idx];
            float4 pr = pr4[idx];
            float tx = t_elem(h.x, pr.x, hx.x);
            float ty = t_elem(h.y, pr.y, hx.y);
            float tz = t_elem(h.z, pr.z, hx.z);
            float tw = t_elem(h.w, pr.w, hx.w);
            p *= ((tx == 0.f) ? 1.f : tx) * ((ty == 0.f) ? 1.f : ty)
               * ((tz == 0.f) ? 1.f : tz) * ((tw == 0.f) ? 1.f : tw);
        }
    }

#pragma unroll
    for (int off = 16; off; off >>= 1) p *= __shfl_xor_sync(0xffffffffu, p, off);
    if ((tid & 31) == 0) warp_prod[tid >> 5] = p;
    __syncthreads();
    if (tid < 16) {
        float q = warp_prod[tid];
#pragma unroll
        for (int off = 8; off; off >>= 1) q *= __shfl_xor_sync(0x0000ffffu, q, off);
        if (tid == 0) g_prod[k] = q;
    }
}

// ---------------- K2b: output writer (WRITE-ONLY stream on fast path) ----------
// prod == 0: every output of the row is EXACTLY clip(2*atanh(+-0)) = 0 -> pure
// zero-write. prod != 0 (general): recompute exact leave-one-out values.
__global__ __launch_bounds__(512) void k_write(const float* __restrict__ Hxs,
                                               const int* __restrict__ H,
                                               const int* __restrict__ x,
                                               float* __restrict__ out_Hxs) {
    int k = blockIdx.x;
    int tid = threadIdx.x;
    float prod = g_prod[k];
    float4* o4 = (float4*)(out_Hxs + (size_t)k * N_DIM);

    if (prod == 0.f) {
        float4 z = make_float4(0.f, 0.f, 0.f, 0.f);
#pragma unroll
        for (int i = 0; i < 4; i++) o4[tid + i * 512] = z;
    } else {
        const float4* hx4 = (const float4*)(Hxs + (size_t)k * N_DIM);
        const int4*   h4  = (const int4*)(H + (size_t)k * N_DIM);
        const float4* pr4 = (const float4*)g_prior;
        bool hxz = (g_hxs_nonzero == 0);
        float s = (float)(1 - 2 * x[k]);
#pragma unroll
        for (int i = 0; i < 4; i++) {
            int idx = tid + i * 512;
            float4 hx = hxz ? make_float4(0.f, 0.f, 0.f, 0.f) : hx4[idx];
            int4   h  = h4[idx];
            float4 pr = pr4[idx];
            float4 o;
            o.x = bp_elem(t_elem(h.x, pr.x, hx.x), prod, s);
            o.y = bp_elem(t_elem(h.y, pr.y, hx.y), prod, s);
            o.z = bp_elem(t_elem(h.z, pr.z, hx.z), prod, s);
            o.w = bp_elem(t_elem(h.w, pr.w, hx.w), prod, s);
            o4[idx] = o;
        }
    }
}

// ---------------- K3: column sum of Hxs_new, skipping all-zero rows ----------------
__global__ __launch_bounds__(256) void k_colsum2(const float* __restrict__ M) {
    const int ROWS = 64;
    int cbase = blockIdx.x * 1024 + threadIdx.x * 4;
    int r0 = blockIdx.y * ROWS;
    const float4* p = (const float4*)(M + (size_t)r0 * N_DIM + cbase);
    float4 a = make_float4(0.f, 0.f, 0.f, 0.f);
    bool any = false;
    for (int r = 0; r < ROWS; r++) {
        if (g_prod[r0 + r] != 0.f) {      // zero-product rows are exactly 0: skip
            any = true;
            float4 v = p[(size_t)r * (N_DIM / 4)];
            a.x += v.x; a.y += v.y; a.z += v.z; a.w += v.w;
        }
    }
    if (any) {
        atomicAdd(&g_colsum2[cbase + 0], a.x);
        atomicAdd(&g_colsum2[cbase + 1], a.y);
        atomicAdd(&g_colsum2[cbase + 2], a.z);
        atomicAdd(&g_colsum2[cbase + 3], a.w);
    }
}

// ---------------- K4: output beliefs ----------------
__global__ void k_out(float* __restrict__ out_M) {
    int n = blockIdx.x * blockDim.x + threadIdx.x;
    if (n >= N_DIM) return;
    float z = (1.f - tanhf((g_colsum2[n] + g_dope[n]) * 0.5f)) * 0.5f;
    out_M[2 * n + 0] = 1.f - z;
    out_M[2 * n + 1] = z;
}

extern "C" void kernel_launch(void* const* d_in, const int* in_sizes, int n_in,
                              void* d_out, int out_size) {
    const float* ps  = (const float*)d_in[0];
    const float* Min = (const float*)d_in[1];
    const float* Hxs = (const float*)d_in[2];
    const int*   x   = (const int*)d_in[3];
    const int*   H   = (const int*)d_in[4];

    float* out     = (float*)d_out;
    float* out_M   = out;                 // M_out [N,2] first
    float* out_Hxs = out + 2 * N_DIM;     // Hxs_new [K,N] second

    k_zero<<<N_DIM / 256, 256>>>();
    k_colsum<<<dim3(N_DIM / 1024, K_DIM / 64), 256>>>(Hxs);
    k_prior<<<N_DIM / 256, 256>>>(ps, Min);
    k_prod<<<K_DIM, 512>>>(Hxs, H);
    k_write<<<K_DIM, 512>>>(Hxs, H, x, out_Hxs);
    k_colsum2<<<dim3(N_DIM / 1024, K_DIM / 64), 256>>>(out_Hxs);
    k_out<<<N_DIM / 256, 256>>>(out_M);
}